// round 16
// baseline (speedup 1.0000x reference)
#include <cuda_runtime.h>
#include <cuda_bf16.h>
#include <cstdint>

#define NB_ 8
#define C_ 64
#define HID_ 128
#define HW_ 65536

// Scratch (device globals; no allocation in kernel_launch)
__device__ __nv_bfloat16 g_h1[(size_t)NB_ * HID_ * HW_];
__device__ __nv_bfloat16 g_h2[(size_t)NB_ * HID_ * HW_];
__device__ float g_pool_part[NB_ * HID_ * 16];
__device__ __nv_bfloat16 g_w1bf[256 * 64];          // prepped bf16 w1
__device__ __nv_bfloat16 g_wbf[NB_ * 64 * HID_];    // per-batch bf16 w3*attn

#define MMA_BF16(d, A, b0r, b1r)                                              \
  asm volatile(                                                               \
      "mma.sync.aligned.m16n8k16.row.col.f32.bf16.bf16.f32 "                  \
      "{%0,%1,%2,%3},{%4,%5,%6,%7},{%8,%9},{%0,%1,%2,%3};\n"                  \
      : "+f"((d)[0]), "+f"((d)[1]), "+f"((d)[2]), "+f"((d)[3])                \
      : "r"((A)[0]), "r"((A)[1]), "r"((A)[2]), "r"((A)[3]), "r"(b0r),         \
        "r"(b1r))

__device__ __forceinline__ void ldsm(unsigned (&r)[4], const __nv_bfloat16* p) {
  unsigned addr = (unsigned)__cvta_generic_to_shared(p);
  asm volatile(
      "ldmatrix.sync.aligned.m8n8.x4.shared.b16 {%0,%1,%2,%3}, [%4];"
      : "=r"(r[0]), "=r"(r[1]), "=r"(r[2]), "=r"(r[3])
      : "r"(addr));
}

__device__ __forceinline__ void ldsm_trans(unsigned (&r)[4],
                                           const __nv_bfloat16* p) {
  unsigned addr = (unsigned)__cvta_generic_to_shared(p);
  asm volatile(
      "ldmatrix.sync.aligned.m8n8.x4.trans.shared.b16 {%0,%1,%2,%3}, [%4];"
      : "=r"(r[0]), "=r"(r[1]), "=r"(r[2]), "=r"(r[3])
      : "r"(addr));
}

__device__ __forceinline__ __nv_bfloat162 u2b(unsigned u) {
  return *reinterpret_cast<__nv_bfloat162*>(&u);
}
__device__ __forceinline__ unsigned b2u(__nv_bfloat162 v) {
  return *reinterpret_cast<unsigned*>(&v);
}

// ---------------------------------------------------------------------------
// K0: one-time prep: w1 -> bf16
// ---------------------------------------------------------------------------
__global__ void k0_prep(const float* __restrict__ w1) {
  int i = blockIdx.x * 256 + threadIdx.x;  // 64 blocks x 256 = 16384
  g_w1bf[i] = __float2bfloat16(w1[i]);
}

// ---------------------------------------------------------------------------
// K1: LayerNorm + 1x1 conv (64->256, bf16 mma) + SimpleGate -> g_h1 (bf16)
// PERSISTENT: grid=296 (2 blocks/SM), weights + ln params loaded ONCE/block.
// (R10 structure — all prefetch variants measured slower.)
// ---------------------------------------------------------------------------
#define K1_OFF_W 0          // w1 bf16 [256][72]          = 36864 B
#define K1_OFF_A 36864      // xn bf16 [64][72]           =  9216 B
#define K1_OFF_B1 46080     // b1 f32  [256]              =  1024 B
#define K1_OFF_LN 47104     // ln_w,ln_b f32 [128]        =   512 B
#define K1_OFF_RED 47616    // LN partials f32 [1024]     =  4096 B
#define K1_OFF_H 51712      // h1 stage bf16 [128][68]    = 17408 B
#define K1_SMEM 69120
#define K1_GRID 296

__global__ void __launch_bounds__(512, 2)
k1_ln_gemm_gate(const float* __restrict__ x, const float* __restrict__ ln_w,
                const float* __restrict__ ln_b, const float* __restrict__ b1) {
  extern __shared__ char sm1[];
  __nv_bfloat16* sW = (__nv_bfloat16*)(sm1 + K1_OFF_W);
  __nv_bfloat16* sA = (__nv_bfloat16*)(sm1 + K1_OFF_A);
  float* sB1 = (float*)(sm1 + K1_OFF_B1);
  float* sLN = (float*)(sm1 + K1_OFF_LN);   // [0:64) ln_w, [64:128) ln_b
  float* sRED = (float*)(sm1 + K1_OFF_RED);
  __nv_bfloat16* sH = (__nv_bfloat16*)(sm1 + K1_OFF_H);

  const int tid = threadIdx.x;

  // weights + params -> smem ONCE
  {
    const uint4* wsrc = (const uint4*)g_w1bf;  // [256][8 uint4]
    uint4* sW4 = (uint4*)sW;                   // stride 9 uint4 (72 bf16)
    for (int i = tid; i < 2048; i += 512) {
      int rr = i >> 3, q = i & 7;
      sW4[rr * 9 + q] = wsrc[i];
    }
  }
  if (tid < 256) sB1[tid] = b1[tid];
  if (tid >= 256 && tid < 320) sLN[tid - 256] = ln_w[tid - 256];
  if (tid >= 320 && tid < 384) sLN[64 + tid - 320] = ln_b[tid - 320];

  const int p = tid & 63, q = tid >> 6;  // q = 0..7
  const int lane = tid & 31, wid = tid >> 5;
  const int lr = lane >> 2, lc = lane & 3;
  const int MB = (wid & 1) * 32;
  const int NBc = (wid >> 1) * 16;
  const int lofs = ((lane >> 3) & 1) * 8 + (lane & 7);  // ldsm row-in-tile
  const int lhi = (lane >> 4) * 8;                      // ldsm k-half

  __syncthreads();  // sLN ready before first LN use

  for (int tile = blockIdx.x; tile < 8192; tile += K1_GRID) {
    const int b = tile >> 10;               // 1024 tiles per image
    const int pix0 = (tile & 1023) << 6;    // 64 pixels per tile

    // load x tile + LayerNorm (8 threads per pixel, 8 channels each)
    const float* xb =
        x + (size_t)b * C_ * HW_ + (size_t)(q * 8) * HW_ + pix0 + p;
    float v[8], s1 = 0.f, s2 = 0.f;
#pragma unroll
    for (int i = 0; i < 8; i++) {
      float t = xb[(size_t)i * HW_];
      v[i] = t;
      s1 += t;
      s2 += t * t;
    }
    sRED[tid] = s1;
    sRED[512 + tid] = s2;
    __syncthreads();
    float t1 = 0.f, t2 = 0.f;
#pragma unroll
    for (int g = 0; g < 8; g++) {
      t1 += sRED[g * 64 + p];
      t2 += sRED[512 + g * 64 + p];
    }
    float mean = t1 * (1.f / 64.f);
    float var = t2 * (1.f / 64.f) - mean * mean;
    float rstd = rsqrtf(var + 1e-6f);
#pragma unroll
    for (int i = 0; i < 8; i++) {
      int c = q * 8 + i;
      float xn = (v[i] - mean) * rstd * sLN[c] + sLN[64 + c];
      sA[p * 72 + c] = __float2bfloat16(xn);
    }
    __syncthreads();

    float acc1[2][2][4], acc2[2][2][4];
#pragma unroll
    for (int mt = 0; mt < 2; mt++)
#pragma unroll
      for (int nt2 = 0; nt2 < 2; nt2++)
#pragma unroll
        for (int r = 0; r < 4; r++) {
          acc1[mt][nt2][r] = 0.f;
          acc2[mt][nt2][r] = 0.f;
        }

#pragma unroll
    for (int ks = 0; ks < 4; ks++) {
      const int kc = ks * 16;
      unsigned a[2][4];
      ldsm(a[0], &sA[(MB + lofs) * 72 + kc + lhi]);
      ldsm(a[1], &sA[(MB + 16 + lofs) * 72 + kc + lhi]);
      unsigned bb1[4], bb2[4];
      ldsm(bb1, &sW[(NBc + lofs) * 72 + kc + lhi]);
      ldsm(bb2, &sW[(NBc + 128 + lofs) * 72 + kc + lhi]);
#pragma unroll
      for (int mt = 0; mt < 2; mt++) {
        MMA_BF16(acc1[mt][0], a[mt], bb1[0], bb1[2]);
        MMA_BF16(acc1[mt][1], a[mt], bb1[1], bb1[3]);
        MMA_BF16(acc2[mt][0], a[mt], bb2[0], bb2[2]);
        MMA_BF16(acc2[mt][1], a[mt], bb2[1], bb2[3]);
      }
    }

    // gate in-register, stage [ch][pixel] in smem
#pragma unroll
    for (int mt = 0; mt < 2; mt++)
#pragma unroll
      for (int nt2 = 0; nt2 < 2; nt2++)
#pragma unroll
        for (int r = 0; r < 4; r++) {
          int row = MB + mt * 16 + lr + ((r & 2) ? 8 : 0);  // px 0..63
          int col = NBc + nt2 * 8 + lc * 2 + (r & 1);       // pair-col
          float y1 = acc1[mt][nt2][r] + sB1[col];
          float y2 = acc2[mt][nt2][r] + sB1[col + 128];
          sH[col * 68 + row] = __float2bfloat16(y1 * y2);
        }
    __syncthreads();

    // coalesced write-out (uint2 = 4 pixels): 128 ch x 16 uint2
    const uint2* sH2 = (const uint2*)sH;  // stride 17 uint2/row
    uint2* out2 = (uint2*)g_h1;
    size_t base2 = (((size_t)b * HID_) * HW_ + pix0) >> 2;
    for (int i = tid; i < 128 * 16; i += 512) {
      int ch = i >> 4, j2 = i & 15;
      out2[base2 + (size_t)ch * (HW_ / 4) + j2] = sH2[ch * 17 + j2];
    }
  }
}

// ---------------------------------------------------------------------------
// K2: grouped 3x3 depthwise + gate + pool partials, bf16x2 SIMD arithmetic.
// 16-row tiles (PROVEN R10 version).
// ---------------------------------------------------------------------------
__global__ void __launch_bounds__(256)
k2_dwconv_gate_pool(const float* __restrict__ w2, const float* __restrict__ b2) {
  __shared__ __nv_bfloat16 sI[2][18 * 272];  // data at cols 8..263
  __shared__ float swb[40];
  __shared__ float sred[512];

  const int rt = blockIdx.x;   // 0..15 row tile
  const int c = blockIdx.y;    // 0..63 channel pair
  const int b = blockIdx.z;    // 0..7
  const int tid = threadIdx.x;

  if (tid < 40) {
    int widx = (tid < 36) ? (tid / 9) : (tid - 36);
    int o = (widx < 2) ? (2 * c + widx) : (128 + 2 * c + widx - 2);
    swb[tid] = (tid < 36) ? w2[o * 9 + tid % 9] : b2[o];
  }

  const int gy0 = rt * 16 - 1;
  const uint4* src0 = (const uint4*)(g_h1 + ((size_t)(b * HID_ + c)) * HW_);
  const uint4* src1 = (const uint4*)(g_h1 + ((size_t)(b * HID_ + 64 + c)) * HW_);
  for (int i = tid; i < 1152; i += 256) {   // 2ch * 18 rows * 32 uint4
    int ch = (i >= 576) ? 1 : 0;
    int j = i - ch * 576;
    int row = j >> 5, k8 = j & 31;
    int gy = gy0 + row;
    uint4 v = make_uint4(0, 0, 0, 0);
    if ((unsigned)gy < 256u) v = (ch ? src1 : src0)[gy * 32 + k8];
    *(uint4*)(&sI[ch][row * 272 + 8 + k8 * 8]) = v;
  }
  if (tid < 72) {  // zero halo cols 7 and 264
    int ch = (tid >= 36) ? 1 : 0;
    int t = tid - ch * 36;
    sI[ch][(t >> 1) * 272 + ((t & 1) ? 264 : 7)] = __float2bfloat16(0.f);
  }
  __syncthreads();

  const int rg = tid >> 6;    // 0..3
  const int cb = tid & 63;    // 0..63
  const int r0 = rg * 4;
  const int sc = 8 + cb * 4;

  // packed weights (both halves identical) + bias packs
  __nv_bfloat162 wp[36];
#pragma unroll
  for (int t = 0; t < 36; t++)
    wp[t] = __bfloat162bfloat162(__float2bfloat16(swb[t]));
  const __nv_bfloat162 bp0 = __bfloat162bfloat162(__float2bfloat16(swb[36]));
  const __nv_bfloat162 bp1 = __bfloat162bfloat162(__float2bfloat16(swb[37]));
  const __nv_bfloat162 bp2 = __bfloat162bfloat162(__float2bfloat16(swb[38]));
  const __nv_bfloat162 bp3 = __bfloat162bfloat162(__float2bfloat16(swb[39]));

#define LDROW2(ch, row, R)                                                    \
  {                                                                           \
    const unsigned* pp_ = (const unsigned*)&sI[ch][(row)*272 + sc - 2];       \
    unsigned r0_ = pp_[0], r1_ = pp_[1], r2_ = pp_[2], r3_ = pp_[3];          \
    R[0] = __byte_perm(r0_, r1_, 0x5432);                                     \
    R[1] = r1_;                                                               \
    R[2] = __byte_perm(r1_, r2_, 0x5432);                                     \
    R[3] = r2_;                                                               \
    R[4] = __byte_perm(r2_, r3_, 0x5432);                                     \
  }

  unsigned RA0[5], RA1[5], RA2[5], RB0[5], RB1[5], RB2[5];
  LDROW2(0, r0, RA0);
  LDROW2(0, r0 + 1, RA1);
  LDROW2(1, r0, RB0);
  LDROW2(1, r0 + 1, RB1);

  __nv_bfloat162 sum0p = __bfloat162bfloat162(__float2bfloat16(0.f));
  __nv_bfloat162 sum1p = sum0p;
  size_t obase =
      ((size_t)(b * HID_ + 2 * c)) * HW_ + (size_t)(rt * 16 + r0) * 256 + cb * 4;

#pragma unroll
  for (int orow = 0; orow < 4; orow++) {
    LDROW2(0, r0 + orow + 2, RA2);
    LDROW2(1, r0 + orow + 2, RB2);
    __nv_bfloat162 a0p0 = bp0, a0p1 = bp0, a1p0 = bp1, a1p1 = bp1;
    __nv_bfloat162 c0p0 = bp2, c0p1 = bp2, c1p0 = bp3, c1p1 = bp3;
#pragma unroll
    for (int j = 0; j < 3; j++) {
      const unsigned* A = (j == 0) ? RA0 : (j == 1) ? RA1 : RA2;
      const unsigned* B = (j == 0) ? RB0 : (j == 1) ? RB1 : RB2;
      a0p0 = __hfma2(u2b(A[0]), wp[j * 3 + 0], a0p0);
      a0p0 = __hfma2(u2b(A[1]), wp[j * 3 + 1], a0p0);
      a0p0 = __hfma2(u2b(A[2]), wp[j * 3 + 2], a0p0);
      a0p1 = __hfma2(u2b(A[2]), wp[j * 3 + 0], a0p1);
      a0p1 = __hfma2(u2b(A[3]), wp[j * 3 + 1], a0p1);
      a0p1 = __hfma2(u2b(A[4]), wp[j * 3 + 2], a0p1);
      a1p0 = __hfma2(u2b(A[0]), wp[9 + j * 3 + 0], a1p0);
      a1p0 = __hfma2(u2b(A[1]), wp[9 + j * 3 + 1], a1p0);
      a1p0 = __hfma2(u2b(A[2]), wp[9 + j * 3 + 2], a1p0);
      a1p1 = __hfma2(u2b(A[2]), wp[9 + j * 3 + 0], a1p1);
      a1p1 = __hfma2(u2b(A[3]), wp[9 + j * 3 + 1], a1p1);
      a1p1 = __hfma2(u2b(A[4]), wp[9 + j * 3 + 2], a1p1);
      c0p0 = __hfma2(u2b(B[0]), wp[18 + j * 3 + 0], c0p0);
      c0p0 = __hfma2(u2b(B[1]), wp[18 + j * 3 + 1], c0p0);
      c0p0 = __hfma2(u2b(B[2]), wp[18 + j * 3 + 2], c0p0);
      c0p1 = __hfma2(u2b(B[2]), wp[18 + j * 3 + 0], c0p1);
      c0p1 = __hfma2(u2b(B[3]), wp[18 + j * 3 + 1], c0p1);
      c0p1 = __hfma2(u2b(B[4]), wp[18 + j * 3 + 2], c0p1);
      c1p0 = __hfma2(u2b(B[0]), wp[27 + j * 3 + 0], c1p0);
      c1p0 = __hfma2(u2b(B[1]), wp[27 + j * 3 + 1], c1p0);
      c1p0 = __hfma2(u2b(B[2]), wp[27 + j * 3 + 2], c1p0);
      c1p1 = __hfma2(u2b(B[2]), wp[27 + j * 3 + 0], c1p1);
      c1p1 = __hfma2(u2b(B[3]), wp[27 + j * 3 + 1], c1p1);
      c1p1 = __hfma2(u2b(B[4]), wp[27 + j * 3 + 2], c1p1);
    }
    __nv_bfloat162 h0p0 = __hmul2(a0p0, c0p0), h0p1 = __hmul2(a0p1, c0p1);
    __nv_bfloat162 h1p0 = __hmul2(a1p0, c1p0), h1p1 = __hmul2(a1p1, c1p1);
    uint2 st0, st1;
    st0.x = b2u(h0p0); st0.y = b2u(h0p1);
    st1.x = b2u(h1p0); st1.y = b2u(h1p1);
    *(uint2*)&g_h2[obase + (size_t)orow * 256] = st0;
    *(uint2*)&g_h2[obase + HW_ + (size_t)orow * 256] = st1;
    sum0p = __hadd2(sum0p, __hadd2(h0p0, h0p1));
    sum1p = __hadd2(sum1p, __hadd2(h1p0, h1p1));
#pragma unroll
    for (int t = 0; t < 5; t++) {
      RA0[t] = RA1[t]; RA1[t] = RA2[t];
      RB0[t] = RB1[t]; RB1[t] = RB2[t];
    }
  }
#undef LDROW2

  float sum0 = __bfloat162float(__low2bfloat16(sum0p)) +
               __bfloat162float(__high2bfloat16(sum0p));
  float sum1 = __bfloat162float(__low2bfloat16(sum1p)) +
               __bfloat162float(__high2bfloat16(sum1p));

  // deterministic per-tile pool partials
  sred[tid] = sum0;
  sred[256 + tid] = sum1;
  __syncthreads();
  for (int s = 128; s > 0; s >>= 1) {
    if (tid < s) {
      sred[tid] += sred[tid + s];
      sred[256 + tid] += sred[256 + tid + s];
    }
    __syncthreads();
  }
  if (tid == 0) {
    g_pool_part[(b * HID_ + 2 * c) * 16 + rt] = sred[0];
    g_pool_part[(b * HID_ + 2 * c + 1) * 16 + rt] = sred[256];
  }
}

// ---------------------------------------------------------------------------
// K3: attn matvec + fold into w3 (grid=8, 1024 threads) — PROVEN 10.2us shape
// ---------------------------------------------------------------------------
__global__ void __launch_bounds__(1024)
k3_attn_fold(const float* __restrict__ w_sca, const float* __restrict__ b_sca,
             const float* __restrict__ w3) {
  __shared__ float sp[HID_];
  __shared__ float sAttn[HID_];
  const int b = blockIdx.x;
  const int t = threadIdx.x;
  if (t < HID_) {
    float s = 0.f;
    const float* pp = g_pool_part + (b * HID_ + t) * 16;
#pragma unroll
    for (int k = 0; k < 16; k++) s += pp[k];
    sp[t] = s * (1.f / 65536.f);
  }
  __syncthreads();
  {
    const int o = t >> 3, j = t & 7;  // 8 threads per output row
    const float* w = w_sca + o * HID_ + j * 16;
    const float* spp = sp + j * 16;
    float acc = 0.f;
#pragma unroll
    for (int k = 0; k < 16; k++) acc += w[k] * spp[k];
    acc += __shfl_down_sync(0xffffffffu, acc, 4, 8);
    acc += __shfl_down_sync(0xffffffffu, acc, 2, 8);
    acc += __shfl_down_sync(0xffffffffu, acc, 1, 8);
    if (j == 0) sAttn[o] = acc + b_sca[o];
  }
  __syncthreads();
  __nv_bfloat16* dst = g_wbf + (size_t)b * 64 * HID_;
  const float av = sAttn[t & 127];
#pragma unroll
  for (int j = 0; j < 8; j++) {
    int i = t + j * 1024;  // (i & 127) == (t & 127)
    dst[i] = __float2bfloat16(w3[i] * av);
  }
}

// ---------------------------------------------------------------------------
// K4: (h2) @ (w3*attn)^T + b3, out = x + beta*h3.  (PROVEN R10 version:
// split-K, staged f32 epilogue through aliased sO, float4 residual.)
// ---------------------------------------------------------------------------
#define K4_OFF_A 0       // h2 bf16 [64 ch][136]    = 17408 B (sO aliases)
#define K4_OFF_W 17408   // wbf bf16 [64 cout][136] = 17408 B
#define K4_SMEM 34816

__global__ void __launch_bounds__(256, 5)
k4_gemm_residual(const float* __restrict__ b3, const float* __restrict__ beta,
                 const float* __restrict__ x, float* __restrict__ out) {
  extern __shared__ char sm4[];
  __nv_bfloat16* sA = (__nv_bfloat16*)(sm4 + K4_OFF_A);   // [64 ch][136]
  __nv_bfloat16* sWB = (__nv_bfloat16*)(sm4 + K4_OFF_W);  // [64 cout][136]
  float* sO = (float*)(sm4);                              // aliases sA+sWB

  const int tid = threadIdx.x;
  const int b = blockIdx.x >> 9;
  const int pix0 = (blockIdx.x & 511) << 7;

  // sWB <- g_wbf[b] (uint4 copy into padded stride)
  {
    const uint4* wsrc = (const uint4*)(g_wbf + (size_t)b * 64 * HID_);
    uint4* sWB4 = (uint4*)sWB;  // stride 17 uint4
    for (int i = tid; i < 1024; i += 256) {
      int o = i >> 4, qq = i & 15;
      sWB4[o * 17 + qq] = wsrc[i];
    }
  }

  const uint4* h2v = (const uint4*)g_h2;
  uint4* sA4 = (uint4*)sA;  // 17 uint4 per row
  size_t base8 = (((size_t)b * HID_) * HW_ + pix0) >> 3;

  const int lane = tid & 31, wid = tid >> 5;
  const int lr = lane >> 2, lc = lane & 3;
  const int MB = (wid & 3) * 32;    // pixel tile (M)
  const int NBc = (wid >> 2) * 32;  // cout tile (N)
  const int lofs = ((lane >> 3) & 1) * 8 + (lane & 7);
  const int lhi = (lane >> 4) * 8;
  const int lkoff = ((lane >> 4) << 3) + (lane & 7);  // trans-ldsm k row
  const int lmoff = ((lane >> 3) & 1) << 3;           // trans-ldsm m half

  float acc[2][4][4];
#pragma unroll
  for (int mt = 0; mt < 2; mt++)
#pragma unroll
    for (int nt = 0; nt < 4; nt++)
#pragma unroll
      for (int r = 0; r < 4; r++) acc[mt][nt][r] = 0.f;

#pragma unroll
  for (int half = 0; half < 2; half++) {
    // sA <- h2 channels [half*64, half*64+64), native [ch][px]
    for (int i = tid; i < 64 * 16; i += 256) {
      int ch = i >> 4, qq = i & 15;
      sA4[ch * 17 + qq] = h2v[base8 + (size_t)(half * 64 + ch) * (HW_ / 8) + qq];
    }
    __syncthreads();
#pragma unroll
    for (int ks = 0; ks < 4; ks++) {
      const int klocal = ks * 16;
      const int kglob = half * 64 + klocal;
      unsigned a[2][4];
      ldsm_trans(a[0], &sA[(klocal + lkoff) * 136 + MB + lmoff]);
      ldsm_trans(a[1], &sA[(klocal + lkoff) * 136 + MB + 16 + lmoff]);
#pragma unroll
      for (int nb = 0; nb < 2; nb++) {
        unsigned bb[4];
        ldsm(bb, &sWB[(NBc + nb * 16 + lofs) * 136 + kglob + lhi]);
        MMA_BF16(acc[0][nb * 2], a[0], bb[0], bb[2]);
        MMA_BF16(acc[1][nb * 2], a[1], bb[0], bb[2]);
        MMA_BF16(acc[0][nb * 2 + 1], a[0], bb[1], bb[3]);
        MMA_BF16(acc[1][nb * 2 + 1], a[1], bb[1], bb[3]);
      }
    }
    __syncthreads();  // before overwriting sA (and before sO epilogue)
  }

  // stage D[px][cout] -> sO[cout][132px]
#pragma unroll
  for (int mt = 0; mt < 2; mt++)
#pragma unroll
    for (int nt = 0; nt < 4; nt++)
#pragma unroll
      for (int r = 0; r < 4; r++) {
        int row = MB + mt * 16 + lr + ((r & 2) ? 8 : 0);  // px
        int col = NBc + nt * 8 + lc * 2 + (r & 1);        // cout
        sO[col * 132 + row] = acc[mt][nt][r];
      }
  __syncthreads();

  // residual + beta, float4 vectorized
  size_t xbase = ((size_t)b * C_) * HW_ + pix0;
  for (int i = tid; i < 64 * 32; i += 256) {
    int o = i >> 5, p4 = (i & 31) * 4;
    float4 hv = *(const float4*)&sO[o * 132 + p4];
    size_t idx = xbase + (size_t)o * HW_ + p4;
    float4 xin = *(const float4*)&x[idx];
    float bbv = b3[o], be = beta[o];
    float4 r;
    r.x = xin.x + (hv.x + bbv) * be;
    r.y = xin.y + (hv.y + bbv) * be;
    r.z = xin.z + (hv.z + bbv) * be;
    r.w = xin.w + (hv.w + bbv) * be;
    *(float4*)&out[idx] = r;
  }
}

// ---------------------------------------------------------------------------
extern "C" void kernel_launch(void* const* d_in, const int* in_sizes, int n_in,
                              void* d_out, int out_size) {
  const float* x = (const float*)d_in[0];
  const float* ln_w = (const float*)d_in[1];
  const float* ln_b = (const float*)d_in[2];
  const float* w1 = (const float*)d_in[3];
  const float* b1 = (const float*)d_in[4];
  const float* w2 = (const float*)d_in[5];
  const float* b2 = (const float*)d_in[6];
  const float* w_sca = (const float*)d_in[7];
  const float* b_sca = (const float*)d_in[8];
  const float* w3 = (const float*)d_in[9];
  const float* b3 = (const float*)d_in[10];
  const float* beta = (const float*)d_in[11];
  float* out = (float*)d_out;

  cudaFuncSetAttribute(k1_ln_gemm_gate,
                       cudaFuncAttributeMaxDynamicSharedMemorySize, K1_SMEM);
  cudaFuncSetAttribute(k4_gemm_residual,
                       cudaFuncAttributeMaxDynamicSharedMemorySize, K4_SMEM);

  k0_prep<<<64, 256>>>(w1);
  k1_ln_gemm_gate<<<K1_GRID, 512, K1_SMEM>>>(x, ln_w, ln_b, b1);
  k2_dwconv_gate_pool<<<dim3(16, 64, 8), 256>>>(w2, b2);
  k3_attn_fold<<<8, 1024>>>(w_sca, b_sca, w3);
  k4_gemm_residual<<<4096, 256, K4_SMEM>>>(b3, beta, x, out);
}

// round 17
// speedup vs baseline: 1.0245x; 1.0245x over previous
#include <cuda_runtime.h>
#include <cuda_bf16.h>
#include <cstdint>

#define NB_ 8
#define C_ 64
#define HID_ 128
#define HW_ 65536

// Scratch (device globals; no allocation in kernel_launch)
__device__ __nv_bfloat16 g_h1[(size_t)NB_ * HID_ * HW_];
__device__ __nv_bfloat16 g_h2[(size_t)NB_ * HID_ * HW_];
__device__ float g_pool_part[NB_ * HID_ * 16];
__device__ __nv_bfloat16 g_w1bf[256 * 64];          // prepped bf16 w1
__device__ __nv_bfloat16 g_wbf[NB_ * 64 * HID_];    // per-batch bf16 w3*attn

#define MMA_BF16(d, A, b0r, b1r)                                              \
  asm volatile(                                                               \
      "mma.sync.aligned.m16n8k16.row.col.f32.bf16.bf16.f32 "                  \
      "{%0,%1,%2,%3},{%4,%5,%6,%7},{%8,%9},{%0,%1,%2,%3};\n"                  \
      : "+f"((d)[0]), "+f"((d)[1]), "+f"((d)[2]), "+f"((d)[3])                \
      : "r"((A)[0]), "r"((A)[1]), "r"((A)[2]), "r"((A)[3]), "r"(b0r),         \
        "r"(b1r))

__device__ __forceinline__ void ldsm(unsigned (&r)[4], const __nv_bfloat16* p) {
  unsigned addr = (unsigned)__cvta_generic_to_shared(p);
  asm volatile(
      "ldmatrix.sync.aligned.m8n8.x4.shared.b16 {%0,%1,%2,%3}, [%4];"
      : "=r"(r[0]), "=r"(r[1]), "=r"(r[2]), "=r"(r[3])
      : "r"(addr));
}

__device__ __forceinline__ void ldsm_trans(unsigned (&r)[4],
                                           const __nv_bfloat16* p) {
  unsigned addr = (unsigned)__cvta_generic_to_shared(p);
  asm volatile(
      "ldmatrix.sync.aligned.m8n8.x4.trans.shared.b16 {%0,%1,%2,%3}, [%4];"
      : "=r"(r[0]), "=r"(r[1]), "=r"(r[2]), "=r"(r[3])
      : "r"(addr));
}

__device__ __forceinline__ __nv_bfloat162 u2b(unsigned u) {
  return *reinterpret_cast<__nv_bfloat162*>(&u);
}
__device__ __forceinline__ unsigned b2u(__nv_bfloat162 v) {
  return *reinterpret_cast<unsigned*>(&v);
}

// ---------------------------------------------------------------------------
// K0: one-time prep: w1 -> bf16
// ---------------------------------------------------------------------------
__global__ void k0_prep(const float* __restrict__ w1) {
  int i = blockIdx.x * 256 + threadIdx.x;  // 64 blocks x 256 = 16384
  g_w1bf[i] = __float2bfloat16(w1[i]);
}

// ---------------------------------------------------------------------------
// K1: LayerNorm + 1x1 conv (64->256, bf16 mma) + SimpleGate -> g_h1 (bf16)
// PERSISTENT: grid=296 (2 blocks/SM), weights loaded ONCE per block.
// EXACT R10 version (measured best).
// ---------------------------------------------------------------------------
#define K1_OFF_W 0          // w1 bf16 [256][72]          = 36864 B
#define K1_OFF_A 36864      // xn bf16 [64][72]           =  9216 B
#define K1_OFF_B1 46080     // b1 f32  [256]              =  1024 B
#define K1_OFF_RED 47104    // LN partials f32 [1024]     =  4096 B
#define K1_OFF_H 51200      // h1 stage bf16 [128][68]    = 17408 B
#define K1_SMEM 68608
#define K1_GRID 296

__global__ void __launch_bounds__(512, 2)
k1_ln_gemm_gate(const float* __restrict__ x, const float* __restrict__ ln_w,
                const float* __restrict__ ln_b, const float* __restrict__ b1) {
  extern __shared__ char sm1[];
  __nv_bfloat16* sW = (__nv_bfloat16*)(sm1 + K1_OFF_W);
  __nv_bfloat16* sA = (__nv_bfloat16*)(sm1 + K1_OFF_A);
  float* sB1 = (float*)(sm1 + K1_OFF_B1);
  float* sRED = (float*)(sm1 + K1_OFF_RED);
  __nv_bfloat16* sH = (__nv_bfloat16*)(sm1 + K1_OFF_H);

  const int tid = threadIdx.x;

  // weights -> smem ONCE (uint4 copy of prepped bf16)
  {
    const uint4* wsrc = (const uint4*)g_w1bf;  // [256][8 uint4]
    uint4* sW4 = (uint4*)sW;                   // stride 9 uint4 (72 bf16)
    for (int i = tid; i < 2048; i += 512) {
      int rr = i >> 3, q = i & 7;
      sW4[rr * 9 + q] = wsrc[i];
    }
  }
  if (tid < 256) sB1[tid] = b1[tid];

  const int p = tid & 63, q = tid >> 6;  // q = 0..7
  const int lane = tid & 31, wid = tid >> 5;
  const int lr = lane >> 2, lc = lane & 3;
  const int MB = (wid & 1) * 32;
  const int NBc = (wid >> 1) * 16;
  const int lofs = ((lane >> 3) & 1) * 8 + (lane & 7);  // ldsm row-in-tile
  const int lhi = (lane >> 4) * 8;                      // ldsm k-half

  for (int tile = blockIdx.x; tile < 8192; tile += K1_GRID) {
    const int b = tile >> 10;               // 1024 tiles per image
    const int pix0 = (tile & 1023) << 6;    // 64 pixels per tile

    // load x tile + LayerNorm (8 threads per pixel, 8 channels each)
    const float* xb =
        x + (size_t)b * C_ * HW_ + (size_t)(q * 8) * HW_ + pix0 + p;
    float v[8], s1 = 0.f, s2 = 0.f;
#pragma unroll
    for (int i = 0; i < 8; i++) {
      float t = xb[(size_t)i * HW_];
      v[i] = t;
      s1 += t;
      s2 += t * t;
    }
    sRED[tid] = s1;
    sRED[512 + tid] = s2;
    __syncthreads();
    float t1 = 0.f, t2 = 0.f;
#pragma unroll
    for (int g = 0; g < 8; g++) {
      t1 += sRED[g * 64 + p];
      t2 += sRED[512 + g * 64 + p];
    }
    float mean = t1 * (1.f / 64.f);
    float var = t2 * (1.f / 64.f) - mean * mean;
    float rstd = rsqrtf(var + 1e-6f);
#pragma unroll
    for (int i = 0; i < 8; i++) {
      int c = q * 8 + i;
      float xn = (v[i] - mean) * rstd * ln_w[c] + ln_b[c];
      sA[p * 72 + c] = __float2bfloat16(xn);
    }
    __syncthreads();

    float acc1[2][2][4], acc2[2][2][4];
#pragma unroll
    for (int mt = 0; mt < 2; mt++)
#pragma unroll
      for (int nt2 = 0; nt2 < 2; nt2++)
#pragma unroll
        for (int r = 0; r < 4; r++) {
          acc1[mt][nt2][r] = 0.f;
          acc2[mt][nt2][r] = 0.f;
        }

#pragma unroll
    for (int ks = 0; ks < 4; ks++) {
      const int kc = ks * 16;
      unsigned a[2][4];
      ldsm(a[0], &sA[(MB + lofs) * 72 + kc + lhi]);
      ldsm(a[1], &sA[(MB + 16 + lofs) * 72 + kc + lhi]);
      unsigned bb1[4], bb2[4];
      ldsm(bb1, &sW[(NBc + lofs) * 72 + kc + lhi]);
      ldsm(bb2, &sW[(NBc + 128 + lofs) * 72 + kc + lhi]);
#pragma unroll
      for (int mt = 0; mt < 2; mt++) {
        MMA_BF16(acc1[mt][0], a[mt], bb1[0], bb1[2]);
        MMA_BF16(acc1[mt][1], a[mt], bb1[1], bb1[3]);
        MMA_BF16(acc2[mt][0], a[mt], bb2[0], bb2[2]);
        MMA_BF16(acc2[mt][1], a[mt], bb2[1], bb2[3]);
      }
    }

    // gate in-register, stage [ch][pixel] in smem
#pragma unroll
    for (int mt = 0; mt < 2; mt++)
#pragma unroll
      for (int nt2 = 0; nt2 < 2; nt2++)
#pragma unroll
        for (int r = 0; r < 4; r++) {
          int row = MB + mt * 16 + lr + ((r & 2) ? 8 : 0);  // px 0..63
          int col = NBc + nt2 * 8 + lc * 2 + (r & 1);       // pair-col
          float y1 = acc1[mt][nt2][r] + sB1[col];
          float y2 = acc2[mt][nt2][r] + sB1[col + 128];
          sH[col * 68 + row] = __float2bfloat16(y1 * y2);
        }
    __syncthreads();

    // coalesced write-out (uint2 = 4 pixels): 128 ch x 16 uint2
    const uint2* sH2 = (const uint2*)sH;  // stride 17 uint2/row
    uint2* out2 = (uint2*)g_h1;
    size_t base2 = (((size_t)b * HID_) * HW_ + pix0) >> 2;
    for (int i = tid; i < 128 * 16; i += 512) {
      int ch = i >> 4, j2 = i & 15;
      out2[base2 + (size_t)ch * (HW_ / 4) + j2] = sH2[ch * 17 + j2];
    }
  }
}

// ---------------------------------------------------------------------------
// K2: grouped 3x3 depthwise + gate + pool partials, bf16x2 SIMD arithmetic.
// 16-row tiles. EXACT R10 version (measured best).
// ---------------------------------------------------------------------------
__global__ void __launch_bounds__(256)
k2_dwconv_gate_pool(const float* __restrict__ w2, const float* __restrict__ b2) {
  __shared__ __nv_bfloat16 sI[2][18 * 272];  // data at cols 8..263
  __shared__ float swb[40];
  __shared__ float sred[512];

  const int rt = blockIdx.x;   // 0..15 row tile
  const int c = blockIdx.y;    // 0..63 channel pair
  const int b = blockIdx.z;    // 0..7
  const int tid = threadIdx.x;

  if (tid < 40) {
    int widx = (tid < 36) ? (tid / 9) : (tid - 36);
    int o = (widx < 2) ? (2 * c + widx) : (128 + 2 * c + widx - 2);
    swb[tid] = (tid < 36) ? w2[o * 9 + tid % 9] : b2[o];
  }

  const int gy0 = rt * 16 - 1;
  const uint4* src0 = (const uint4*)(g_h1 + ((size_t)(b * HID_ + c)) * HW_);
  const uint4* src1 = (const uint4*)(g_h1 + ((size_t)(b * HID_ + 64 + c)) * HW_);
  for (int i = tid; i < 1152; i += 256) {   // 2ch * 18 rows * 32 uint4
    int ch = (i >= 576) ? 1 : 0;
    int j = i - ch * 576;
    int row = j >> 5, k8 = j & 31;
    int gy = gy0 + row;
    uint4 v = make_uint4(0, 0, 0, 0);
    if ((unsigned)gy < 256u) v = (ch ? src1 : src0)[gy * 32 + k8];
    *(uint4*)(&sI[ch][row * 272 + 8 + k8 * 8]) = v;
  }
  if (tid < 72) {  // zero halo cols 7 and 264
    int ch = (tid >= 36) ? 1 : 0;
    int t = tid - ch * 36;
    sI[ch][(t >> 1) * 272 + ((t & 1) ? 264 : 7)] = __float2bfloat16(0.f);
  }
  __syncthreads();

  const int rg = tid >> 6;    // 0..3
  const int cb = tid & 63;    // 0..63
  const int r0 = rg * 4;
  const int sc = 8 + cb * 4;

  // packed weights (both halves identical) + bias packs
  __nv_bfloat162 wp[36];
#pragma unroll
  for (int t = 0; t < 36; t++)
    wp[t] = __bfloat162bfloat162(__float2bfloat16(swb[t]));
  const __nv_bfloat162 bp0 = __bfloat162bfloat162(__float2bfloat16(swb[36]));
  const __nv_bfloat162 bp1 = __bfloat162bfloat162(__float2bfloat16(swb[37]));
  const __nv_bfloat162 bp2 = __bfloat162bfloat162(__float2bfloat16(swb[38]));
  const __nv_bfloat162 bp3 = __bfloat162bfloat162(__float2bfloat16(swb[39]));

#define LDROW2(ch, row, R)                                                    \
  {                                                                           \
    const unsigned* pp_ = (const unsigned*)&sI[ch][(row)*272 + sc - 2];       \
    unsigned r0_ = pp_[0], r1_ = pp_[1], r2_ = pp_[2], r3_ = pp_[3];          \
    R[0] = __byte_perm(r0_, r1_, 0x5432);                                     \
    R[1] = r1_;                                                               \
    R[2] = __byte_perm(r1_, r2_, 0x5432);                                     \
    R[3] = r2_;                                                               \
    R[4] = __byte_perm(r2_, r3_, 0x5432);                                     \
  }

  unsigned RA0[5], RA1[5], RA2[5], RB0[5], RB1[5], RB2[5];
  LDROW2(0, r0, RA0);
  LDROW2(0, r0 + 1, RA1);
  LDROW2(1, r0, RB0);
  LDROW2(1, r0 + 1, RB1);

  __nv_bfloat162 sum0p = __bfloat162bfloat162(__float2bfloat16(0.f));
  __nv_bfloat162 sum1p = sum0p;
  size_t obase =
      ((size_t)(b * HID_ + 2 * c)) * HW_ + (size_t)(rt * 16 + r0) * 256 + cb * 4;

#pragma unroll
  for (int orow = 0; orow < 4; orow++) {
    LDROW2(0, r0 + orow + 2, RA2);
    LDROW2(1, r0 + orow + 2, RB2);
    __nv_bfloat162 a0p0 = bp0, a0p1 = bp0, a1p0 = bp1, a1p1 = bp1;
    __nv_bfloat162 c0p0 = bp2, c0p1 = bp2, c1p0 = bp3, c1p1 = bp3;
#pragma unroll
    for (int j = 0; j < 3; j++) {
      const unsigned* A = (j == 0) ? RA0 : (j == 1) ? RA1 : RA2;
      const unsigned* B = (j == 0) ? RB0 : (j == 1) ? RB1 : RB2;
      a0p0 = __hfma2(u2b(A[0]), wp[j * 3 + 0], a0p0);
      a0p0 = __hfma2(u2b(A[1]), wp[j * 3 + 1], a0p0);
      a0p0 = __hfma2(u2b(A[2]), wp[j * 3 + 2], a0p0);
      a0p1 = __hfma2(u2b(A[2]), wp[j * 3 + 0], a0p1);
      a0p1 = __hfma2(u2b(A[3]), wp[j * 3 + 1], a0p1);
      a0p1 = __hfma2(u2b(A[4]), wp[j * 3 + 2], a0p1);
      a1p0 = __hfma2(u2b(A[0]), wp[9 + j * 3 + 0], a1p0);
      a1p0 = __hfma2(u2b(A[1]), wp[9 + j * 3 + 1], a1p0);
      a1p0 = __hfma2(u2b(A[2]), wp[9 + j * 3 + 2], a1p0);
      a1p1 = __hfma2(u2b(A[2]), wp[9 + j * 3 + 0], a1p1);
      a1p1 = __hfma2(u2b(A[3]), wp[9 + j * 3 + 1], a1p1);
      a1p1 = __hfma2(u2b(A[4]), wp[9 + j * 3 + 2], a1p1);
      c0p0 = __hfma2(u2b(B[0]), wp[18 + j * 3 + 0], c0p0);
      c0p0 = __hfma2(u2b(B[1]), wp[18 + j * 3 + 1], c0p0);
      c0p0 = __hfma2(u2b(B[2]), wp[18 + j * 3 + 2], c0p0);
      c0p1 = __hfma2(u2b(B[2]), wp[18 + j * 3 + 0], c0p1);
      c0p1 = __hfma2(u2b(B[3]), wp[18 + j * 3 + 1], c0p1);
      c0p1 = __hfma2(u2b(B[4]), wp[18 + j * 3 + 2], c0p1);
      c1p0 = __hfma2(u2b(B[0]), wp[27 + j * 3 + 0], c1p0);
      c1p0 = __hfma2(u2b(B[1]), wp[27 + j * 3 + 1], c1p0);
      c1p0 = __hfma2(u2b(B[2]), wp[27 + j * 3 + 2], c1p0);
      c1p1 = __hfma2(u2b(B[2]), wp[27 + j * 3 + 0], c1p1);
      c1p1 = __hfma2(u2b(B[3]), wp[27 + j * 3 + 1], c1p1);
      c1p1 = __hfma2(u2b(B[4]), wp[27 + j * 3 + 2], c1p1);
    }
    __nv_bfloat162 h0p0 = __hmul2(a0p0, c0p0), h0p1 = __hmul2(a0p1, c0p1);
    __nv_bfloat162 h1p0 = __hmul2(a1p0, c1p0), h1p1 = __hmul2(a1p1, c1p1);
    uint2 st0, st1;
    st0.x = b2u(h0p0); st0.y = b2u(h0p1);
    st1.x = b2u(h1p0); st1.y = b2u(h1p1);
    *(uint2*)&g_h2[obase + (size_t)orow * 256] = st0;
    *(uint2*)&g_h2[obase + HW_ + (size_t)orow * 256] = st1;
    sum0p = __hadd2(sum0p, __hadd2(h0p0, h0p1));
    sum1p = __hadd2(sum1p, __hadd2(h1p0, h1p1));
#pragma unroll
    for (int t = 0; t < 5; t++) {
      RA0[t] = RA1[t]; RA1[t] = RA2[t];
      RB0[t] = RB1[t]; RB1[t] = RB2[t];
    }
  }
#undef LDROW2

  float sum0 = __bfloat162float(__low2bfloat16(sum0p)) +
               __bfloat162float(__high2bfloat16(sum0p));
  float sum1 = __bfloat162float(__low2bfloat16(sum1p)) +
               __bfloat162float(__high2bfloat16(sum1p));

  // deterministic per-tile pool partials
  sred[tid] = sum0;
  sred[256 + tid] = sum1;
  __syncthreads();
  for (int s = 128; s > 0; s >>= 1) {
    if (tid < s) {
      sred[tid] += sred[tid + s];
      sred[256 + tid] += sred[256 + tid + s];
    }
    __syncthreads();
  }
  if (tid == 0) {
    g_pool_part[(b * HID_ + 2 * c) * 16 + rt] = sred[0];
    g_pool_part[(b * HID_ + 2 * c + 1) * 16 + rt] = sred[256];
  }
}

// ---------------------------------------------------------------------------
// K3: attn matvec + fold into w3 (grid=8, 1024 threads) — PROVEN 10.2us shape
// ---------------------------------------------------------------------------
__global__ void __launch_bounds__(1024)
k3_attn_fold(const float* __restrict__ w_sca, const float* __restrict__ b_sca,
             const float* __restrict__ w3) {
  __shared__ float sp[HID_];
  __shared__ float sAttn[HID_];
  const int b = blockIdx.x;
  const int t = threadIdx.x;
  if (t < HID_) {
    float s = 0.f;
    const float* pp = g_pool_part + (b * HID_ + t) * 16;
#pragma unroll
    for (int k = 0; k < 16; k++) s += pp[k];
    sp[t] = s * (1.f / 65536.f);
  }
  __syncthreads();
  {
    const int o = t >> 3, j = t & 7;  // 8 threads per output row
    const float* w = w_sca + o * HID_ + j * 16;
    const float* spp = sp + j * 16;
    float acc = 0.f;
#pragma unroll
    for (int k = 0; k < 16; k++) acc += w[k] * spp[k];
    acc += __shfl_down_sync(0xffffffffu, acc, 4, 8);
    acc += __shfl_down_sync(0xffffffffu, acc, 2, 8);
    acc += __shfl_down_sync(0xffffffffu, acc, 1, 8);
    if (j == 0) sAttn[o] = acc + b_sca[o];
  }
  __syncthreads();
  __nv_bfloat16* dst = g_wbf + (size_t)b * 64 * HID_;
  const float av = sAttn[t & 127];
#pragma unroll
  for (int j = 0; j < 8; j++) {
    int i = t + j * 1024;  // (i & 127) == (t & 127)
    dst[i] = __float2bfloat16(w3[i] * av);
  }
}

// ---------------------------------------------------------------------------
// K4: (h2) @ (w3*attn)^T + b3, out = x + beta*h3.  EXACT R10 version:
// split-K, staged f32 epilogue through aliased sO, float4 residual.
// ---------------------------------------------------------------------------
#define K4_OFF_A 0       // h2 bf16 [64 ch][136]    = 17408 B (sO aliases)
#define K4_OFF_W 17408   // wbf bf16 [64 cout][136] = 17408 B
#define K4_SMEM 34816

__global__ void __launch_bounds__(256, 5)
k4_gemm_residual(const float* __restrict__ b3, const float* __restrict__ beta,
                 const float* __restrict__ x, float* __restrict__ out) {
  extern __shared__ char sm4[];
  __nv_bfloat16* sA = (__nv_bfloat16*)(sm4 + K4_OFF_A);   // [64 ch][136]
  __nv_bfloat16* sWB = (__nv_bfloat16*)(sm4 + K4_OFF_W);  // [64 cout][136]
  float* sO = (float*)(sm4);                              // aliases sA+sWB

  const int tid = threadIdx.x;
  const int b = blockIdx.x >> 9;
  const int pix0 = (blockIdx.x & 511) << 7;

  // sWB <- g_wbf[b] (uint4 copy into padded stride)
  {
    const uint4* wsrc = (const uint4*)(g_wbf + (size_t)b * 64 * HID_);
    uint4* sWB4 = (uint4*)sWB;  // stride 17 uint4
    for (int i = tid; i < 1024; i += 256) {
      int o = i >> 4, qq = i & 15;
      sWB4[o * 17 + qq] = wsrc[i];
    }
  }

  const uint4* h2v = (const uint4*)g_h2;
  uint4* sA4 = (uint4*)sA;  // 17 uint4 per row
  size_t base8 = (((size_t)b * HID_) * HW_ + pix0) >> 3;

  const int lane = tid & 31, wid = tid >> 5;
  const int lr = lane >> 2, lc = lane & 3;
  const int MB = (wid & 3) * 32;    // pixel tile (M)
  const int NBc = (wid >> 2) * 32;  // cout tile (N)
  const int lofs = ((lane >> 3) & 1) * 8 + (lane & 7);
  const int lhi = (lane >> 4) * 8;
  const int lkoff = ((lane >> 4) << 3) + (lane & 7);  // trans-ldsm k row
  const int lmoff = ((lane >> 3) & 1) << 3;           // trans-ldsm m half

  float acc[2][4][4];
#pragma unroll
  for (int mt = 0; mt < 2; mt++)
#pragma unroll
    for (int nt = 0; nt < 4; nt++)
#pragma unroll
      for (int r = 0; r < 4; r++) acc[mt][nt][r] = 0.f;

#pragma unroll
  for (int half = 0; half < 2; half++) {
    // sA <- h2 channels [half*64, half*64+64), native [ch][px]
    for (int i = tid; i < 64 * 16; i += 256) {
      int ch = i >> 4, qq = i & 15;
      sA4[ch * 17 + qq] = h2v[base8 + (size_t)(half * 64 + ch) * (HW_ / 8) + qq];
    }
    __syncthreads();
#pragma unroll
    for (int ks = 0; ks < 4; ks++) {
      const int klocal = ks * 16;
      const int kglob = half * 64 + klocal;
      unsigned a[2][4];
      ldsm_trans(a[0], &sA[(klocal + lkoff) * 136 + MB + lmoff]);
      ldsm_trans(a[1], &sA[(klocal + lkoff) * 136 + MB + 16 + lmoff]);
#pragma unroll
      for (int nb = 0; nb < 2; nb++) {
        unsigned bb[4];
        ldsm(bb, &sWB[(NBc + nb * 16 + lofs) * 136 + kglob + lhi]);
        MMA_BF16(acc[0][nb * 2], a[0], bb[0], bb[2]);
        MMA_BF16(acc[1][nb * 2], a[1], bb[0], bb[2]);
        MMA_BF16(acc[0][nb * 2 + 1], a[0], bb[1], bb[3]);
        MMA_BF16(acc[1][nb * 2 + 1], a[1], bb[1], bb[3]);
      }
    }
    __syncthreads();  // before overwriting sA (and before sO epilogue)
  }

  // stage D[px][cout] -> sO[cout][132px]
#pragma unroll
  for (int mt = 0; mt < 2; mt++)
#pragma unroll
    for (int nt = 0; nt < 4; nt++)
#pragma unroll
      for (int r = 0; r < 4; r++) {
        int row = MB + mt * 16 + lr + ((r & 2) ? 8 : 0);  // px
        int col = NBc + nt * 8 + lc * 2 + (r & 1);        // cout
        sO[col * 132 + row] = acc[mt][nt][r];
      }
  __syncthreads();

  // residual + beta, float4 vectorized
  size_t xbase = ((size_t)b * C_) * HW_ + pix0;
  for (int i = tid; i < 64 * 32; i += 256) {
    int o = i >> 5, p4 = (i & 31) * 4;
    float4 hv = *(const float4*)&sO[o * 132 + p4];
    size_t idx = xbase + (size_t)o * HW_ + p4;
    float4 xin = *(const float4*)&x[idx];
    float bbv = b3[o], be = beta[o];
    float4 r;
    r.x = xin.x + (hv.x + bbv) * be;
    r.y = xin.y + (hv.y + bbv) * be;
    r.z = xin.z + (hv.z + bbv) * be;
    r.w = xin.w + (hv.w + bbv) * be;
    *(float4*)&out[idx] = r;
  }
}

// ---------------------------------------------------------------------------
extern "C" void kernel_launch(void* const* d_in, const int* in_sizes, int n_in,
                              void* d_out, int out_size) {
  const float* x = (const float*)d_in[0];
  const float* ln_w = (const float*)d_in[1];
  const float* ln_b = (const float*)d_in[2];
  const float* w1 = (const float*)d_in[3];
  const float* b1 = (const float*)d_in[4];
  const float* w2 = (const float*)d_in[5];
  const float* b2 = (const float*)d_in[6];
  const float* w_sca = (const float*)d_in[7];
  const float* b_sca = (const float*)d_in[8];
  const float* w3 = (const float*)d_in[9];
  const float* b3 = (const float*)d_in[10];
  const float* beta = (const float*)d_in[11];
  float* out = (float*)d_out;

  cudaFuncSetAttribute(k1_ln_gemm_gate,
                       cudaFuncAttributeMaxDynamicSharedMemorySize, K1_SMEM);
  cudaFuncSetAttribute(k4_gemm_residual,
                       cudaFuncAttributeMaxDynamicSharedMemorySize, K4_SMEM);

  k0_prep<<<64, 256>>>(w1);
  k1_ln_gemm_gate<<<K1_GRID, 512, K1_SMEM>>>(x, ln_w, ln_b, b1);
  k2_dwconv_gate_pool<<<dim3(16, 64, 8), 256>>>(w2, b2);
  k3_attn_fold<<<8, 1024>>>(w_sca, b_sca, w3);
  k4_gemm_residual<<<4096, 256, K4_SMEM>>>(b3, beta, x, out);
}